// round 8
// baseline (speedup 1.0000x reference)
#include <cuda_runtime.h>
#include <math.h>

// VolatilityLoss: mean((std3(pred) - std3(targ))^2), window w=3.
// B=512, S=8192, L=8190 outputs/row.
// Packed f32x2 difference chain: pred in lo lane, targ in hi lane.
// 6*var_i = e_i^2 + e_{i+1}^2 + (e_i+e_{i+1})^2, e_i = x_i - x_{i+1}.
// (sqrt(vp)-sqrt(vt))^2 = (vp6 + vt6 - 2*sqrt(vp6*vt6)) / 6  (deferred /6).
// 16 contiguous outputs/thread, 8 front-batched LDG.128, fused finalize.

#define B_ROWS 512
#define S_LEN  8192
#define L_OUT  (S_LEN - 2)            // 8190
#define NBLOCKS 1024
#define NTHREADS 256
// NBLOCKS*NTHREADS*16 == B_ROWS*S_LEN exactly

typedef unsigned long long u64;

__device__ float        g_partials[NBLOCKS];
__device__ unsigned int g_counter = 0;   // monotone across graph replays

__device__ __forceinline__ float sqrt_approx(float x) {
    float r;
    asm("sqrt.approx.f32 %0, %1;" : "=f"(r) : "f"(x));
    return r;
}

#define PACK2(dst, lo, hi) \
    asm("mov.b64 %0, {%1, %2};" : "=l"(dst) : "f"(lo), "f"(hi))
#define UNPACK2(lo, hi, src) \
    asm("mov.b64 {%0, %1}, %2;" : "=f"(lo), "=f"(hi) : "l"(src))
#define FMA2(dst, a, b, c) \
    asm("fma.rn.f32x2 %0, %1, %2, %3;" : "=l"(dst) : "l"(a), "l"(b), "l"(c))
#define ADD2(dst, a, b) \
    asm("add.rn.f32x2 %0, %1, %2;" : "=l"(dst) : "l"(a), "l"(b))
#define MUL2(dst, a, b) \
    asm("mul.rn.f32x2 %0, %1, %2;" : "=l"(dst) : "l"(a), "l"(b))

__global__ void __launch_bounds__(NTHREADS)
vol_loss_fused(const float* __restrict__ pred, const float* __restrict__ targ,
               float* __restrict__ out) {
    const int g    = blockIdx.x * NTHREADS + threadIdx.x;
    const int lane = threadIdx.x & 31;
    const int row   = g >> 9;            // 512 16-spans per row
    const int start = (g & 511) << 4;

    const float* pb = pred + ((size_t)row << 13) + start;
    const float* tb = targ + ((size_t)row << 13) + start;

    // 8 independent LDG.128, front-batched.
    float4 pA = ((const float4*)pb)[0];
    float4 pB = ((const float4*)pb)[1];
    float4 pC = ((const float4*)pb)[2];
    float4 pD = ((const float4*)pb)[3];
    float4 tA = ((const float4*)tb)[0];
    float4 tB = ((const float4*)tb)[1];
    float4 tC = ((const float4*)tb)[2];
    float4 tD = ((const float4*)tb)[3];

    // Elements 16,17 of my span = lane+1's elements 0,1; row end (always lane
    // 31) loads them predicated (its windows 14,15 are invalid anyway).
    bool full = (start + 16) < S_LEN;
    float p16 = __shfl_down_sync(0xffffffffu, pA.x, 1);
    float p17 = __shfl_down_sync(0xffffffffu, pA.y, 1);
    float t16 = __shfl_down_sync(0xffffffffu, tA.x, 1);
    float t17 = __shfl_down_sync(0xffffffffu, tA.y, 1);
    if (lane == 31) {
        p16 = p17 = t16 = t17 = 0.0f;
        if (full) {
            float2 pe2 = ((const float2*)(pb + 16))[0];
            float2 te2 = ((const float2*)(tb + 16))[0];
            p16 = pe2.x; p17 = pe2.y; t16 = te2.x; t17 = te2.y;
        }
    }

    // Pack {pred, targ} pairs into f32x2 registers.
    u64 W[18];
    PACK2(W[0],  pA.x, tA.x);  PACK2(W[1],  pA.y, tA.y);
    PACK2(W[2],  pA.z, tA.z);  PACK2(W[3],  pA.w, tA.w);
    PACK2(W[4],  pB.x, tB.x);  PACK2(W[5],  pB.y, tB.y);
    PACK2(W[6],  pB.z, tB.z);  PACK2(W[7],  pB.w, tB.w);
    PACK2(W[8],  pC.x, tC.x);  PACK2(W[9],  pC.y, tC.y);
    PACK2(W[10], pC.z, tC.z);  PACK2(W[11], pC.w, tC.w);
    PACK2(W[12], pD.x, tD.x);  PACK2(W[13], pD.y, tD.y);
    PACK2(W[14], pD.z, tD.z);  PACK2(W[15], pD.w, tD.w);
    PACK2(W[16], p16,  t16);   PACK2(W[17], p17,  t17);

    u64 M1, accV;
    PACK2(M1,   -1.0f, -1.0f);
    PACK2(accV,  0.0f,  0.0f);
    float accR = 0.0f;

    // Rolling packed difference chain: lo lane = pred, hi lane = targ.
    u64 Ep, Gp;
    FMA2(Ep, W[1], M1, W[0]);     // e0 = w0 - w1 (both lanes)
    MUL2(Gp, Ep, Ep);
    #pragma unroll
    for (int j = 0; j < 16; ++j) {
        u64 E, Gc, F, GS, V;
        FMA2(E, W[j + 2], M1, W[j + 1]);
        MUL2(Gc, E, E);
        ADD2(F, Ep, E);
        ADD2(GS, Gp, Gc);
        FMA2(V, F, F, GS);          // {6*var_p, 6*var_t}, both >= 0
        if (j < 14 || full) {
            ADD2(accV, accV, V);
            float vp, vt;
            UNPACK2(vp, vt, V);
            accR += sqrt_approx(vp * vt);
        }
        Ep = E; Gp = Gc;
    }

    float vps, vts;
    UNPACK2(vps, vts, accV);
    float acc = (vps + vts) - 2.0f * accR;   // still scaled by 6

    // Deterministic intra-block reduction.
    #pragma unroll
    for (int o = 16; o > 0; o >>= 1)
        acc += __shfl_down_sync(0xffffffffu, acc, o);

    __shared__ float red[NTHREADS / 32];
    int warp = threadIdx.x >> 5;
    if (lane == 0) red[warp] = acc;
    __syncthreads();

    __shared__ bool is_last;
    if (threadIdx.x == 0) {
        float v = 0.0f;
        #pragma unroll
        for (int w = 0; w < NTHREADS / 32; ++w) v += red[w];
        g_partials[blockIdx.x] = v;
        __threadfence();
        unsigned int old = atomicAdd(&g_counter, 1u);
        is_last = ((old + 1u) % (unsigned)NBLOCKS) == 0u;
    }
    __syncthreads();

    if (!is_last) return;

    // Last block: deterministic final reduction; fold the deferred /6 here.
    __shared__ double sh[NTHREADS];
    double s = 0.0;
    for (int i = threadIdx.x; i < NBLOCKS; i += NTHREADS)
        s += (double)g_partials[i];
    sh[threadIdx.x] = s;
    __syncthreads();
    #pragma unroll
    for (int stride = NTHREADS / 2; stride > 0; stride >>= 1) {
        if (threadIdx.x < stride) sh[threadIdx.x] += sh[threadIdx.x + stride];
        __syncthreads();
    }
    if (threadIdx.x == 0)
        out[0] = (float)(sh[0] / (6.0 * (double)B_ROWS * (double)L_OUT));
}

extern "C" void kernel_launch(void* const* d_in, const int* in_sizes, int n_in,
                              void* d_out, int out_size) {
    const float* pred = (const float*)d_in[0];
    const float* targ = (const float*)d_in[1];
    vol_loss_fused<<<NBLOCKS, NTHREADS>>>(pred, targ, (float*)d_out);
}